// round 6
// baseline (speedup 1.0000x reference)
#include <cuda_runtime.h>
#include <math.h>

#define N_DIM    64
#define B_ROWS   1024
#define QCH      32
#define NBLK_KDE (N_DIM * QCH)      // 2048
#define NGRP     64                 // knn row-groups of 16
#define NQ       4                  // j-quarters per group
#define NBLK_KNN (NGRP * NQ)        // 256
#define ZF       0.84932157f        // sqrt(0.5*log2 e): ex2(-(ZF a)^2) = exp(-a^2/2)
#define TS4      3.39728628f        // 4.0 * ZF

// Scratch (device globals — no allocation allowed)
__device__ float g_logrho[B_ROWS];
__device__ float g_cols[N_DIM * B_ROWS];
__device__ float g_invh[N_DIM];
__device__ float g_zih[N_DIM];
__device__ float g_partials[N_DIM * QCH];
__device__ float g_t6[NGRP][NQ][16][6];
__device__ int   g_qc[NGRP];        // self-resetting quarter counters
__device__ int   g_done;

__device__ __forceinline__ float ex2(float x) {
    float r;
    asm("ex2.approx.ftz.f32 %0, %1;" : "=f"(r) : "f"(x));
    return r;
}

// ---------------------------------------------------------------------------
// Kernel 1: knn (blocks 0..255, GEMM-tiled) + prep (blocks 256..319)
// ---------------------------------------------------------------------------
struct KnnS {
    float As[16][64];        // row-major A strip
    float Bs[64][132];       // transposed B tile [k][j], pad 132
    float jn[128];
    float qn[16];
    int   merge;
};
struct PrepS {
    float u[B_ROWS];
    float red[128];
    float scale;
};

__global__ __launch_bounds__(128)
void k1(const float* __restrict__ act, const int* __restrict__ kp) {
    __shared__ __align__(16) char sm[sizeof(KnnS)];
    const int tid = threadIdx.x;
    const int bx  = blockIdx.x;

    if (bx == 0 && tid == 0) g_done = 0;

    if (bx < NBLK_KNN) {
        KnnS* S = (KnnS*)sm;
        const int g = bx >> 2, q = bx & 3;
        const int row0 = g * 16, jbase = q * 256;
        const int lane = tid & 31, w = tid >> 5;
        const int tcol = lane;           // 4 js:  tcol*4 .. +3
        const int trow = w;              // 4 rows: trow*4 .. +3

        // load A strip (16 rows x 64), coalesced float4
        {
            const float4* src = (const float4*)(act + row0 * N_DIM);
            ((float4*)S->As)[tid]       = src[tid];
            ((float4*)S->As)[tid + 128] = src[tid + 128];
        }
        __syncthreads();
        // row norms qn[16]: 8 threads per row
        {
            int r = tid >> 3, seg = tid & 7;
            const float* row = S->As[r];
            float s = 0.f;
            #pragma unroll
            for (int i = 0; i < 8; i++) { float v = row[seg * 8 + i]; s += v * v; }
            #pragma unroll
            for (int off = 4; off; off >>= 1) s += __shfl_down_sync(0xffffffffu, s, off);
            if (seg == 0) S->qn[r] = s;
        }

        float top[4][6];
        #pragma unroll
        for (int r = 0; r < 4; r++)
            #pragma unroll
            for (int i = 0; i < 6; i++) top[r][i] = 3.4e38f;
        float qn4[4];

        for (int t = 0; t < 2; t++) {
            const int jb = jbase + t * 128;
            __syncthreads();   // Bs reuse protection
            // transpose load: warp w loads local js [w*32, w*32+32)
            #pragma unroll
            for (int jq = 0; jq < 8; jq++) {
                int jl = w * 32 + jq * 4;
                int jg = jb + jl;
                #pragma unroll
                for (int kh = 0; kh < 2; kh++) {
                    int k = kh * 32 + lane;
                    float v0 = act[(jg + 0) * N_DIM + k];
                    float v1 = act[(jg + 1) * N_DIM + k];
                    float v2 = act[(jg + 2) * N_DIM + k];
                    float v3 = act[(jg + 3) * N_DIM + k];
                    *(float4*)&S->Bs[k][jl] = make_float4(v0, v1, v2, v3);
                }
            }
            __syncthreads();
            // j norms (conflict-free column sums)
            {
                float s = 0.f;
                #pragma unroll 16
                for (int k = 0; k < 64; k++) { float v = S->Bs[k][tid]; s += v * v; }
                S->jn[tid] = s;
            }
            __syncthreads();
            if (t == 0) {
                #pragma unroll
                for (int r = 0; r < 4; r++) qn4[r] = S->qn[trow * 4 + r];
            }

            // 4x4 register-tiled dot products over k=64
            float acc[4][4];
            #pragma unroll
            for (int r = 0; r < 4; r++)
                #pragma unroll
                for (int c = 0; c < 4; c++) acc[r][c] = 0.f;

            #pragma unroll 4
            for (int kq = 0; kq < 16; kq++) {
                const float4 a0 = *(const float4*)&S->As[trow * 4 + 0][kq * 4];
                const float4 a1 = *(const float4*)&S->As[trow * 4 + 1][kq * 4];
                const float4 a2 = *(const float4*)&S->As[trow * 4 + 2][kq * 4];
                const float4 a3 = *(const float4*)&S->As[trow * 4 + 3][kq * 4];
                const float4 b0 = *(const float4*)&S->Bs[kq * 4 + 0][tcol * 4];
                const float4 b1 = *(const float4*)&S->Bs[kq * 4 + 1][tcol * 4];
                const float4 b2 = *(const float4*)&S->Bs[kq * 4 + 2][tcol * 4];
                const float4 b3 = *(const float4*)&S->Bs[kq * 4 + 3][tcol * 4];
                #define DOT_R(r, ar) \
                    acc[r][0] = fmaf(ar.x, b0.x, fmaf(ar.y, b1.x, fmaf(ar.z, b2.x, fmaf(ar.w, b3.x, acc[r][0])))); \
                    acc[r][1] = fmaf(ar.x, b0.y, fmaf(ar.y, b1.y, fmaf(ar.z, b2.y, fmaf(ar.w, b3.y, acc[r][1])))); \
                    acc[r][2] = fmaf(ar.x, b0.z, fmaf(ar.y, b1.z, fmaf(ar.z, b2.z, fmaf(ar.w, b3.z, acc[r][2])))); \
                    acc[r][3] = fmaf(ar.x, b0.w, fmaf(ar.y, b1.w, fmaf(ar.z, b2.w, fmaf(ar.w, b3.w, acc[r][3]))));
                DOT_R(0, a0) DOT_R(1, a1) DOT_R(2, a2) DOT_R(3, a3)
                #undef DOT_R
            }
            // candidates: dist = qn + jn - 2 dot
            float jn4[4];
            #pragma unroll
            for (int c = 0; c < 4; c++) jn4[c] = S->jn[tcol * 4 + c];
            #pragma unroll
            for (int r = 0; r < 4; r++) {
                #pragma unroll
                for (int c = 0; c < 4; c++) {
                    float v = fmaf(acc[r][c], -2.f, qn4[r] + jn4[c]);
                    if (v < top[r][5]) {
                        top[r][5] = v;
                        #pragma unroll
                        for (int i = 5; i > 0; i--)
                            if (top[r][i] < top[r][i - 1]) {
                                float tm = top[r][i]; top[r][i] = top[r][i - 1]; top[r][i - 1] = tm;
                            }
                    }
                }
            }
        }

        // per-row: extract 6 global minima over 32 lanes, write sorted list
        #pragma unroll
        for (int r = 0; r < 4; r++) {
            float l0 = top[r][0], l1 = top[r][1], l2 = top[r][2];
            float l3 = top[r][3], l4 = top[r][4], l5 = top[r][5];
            float keep = 3.4e38f;
            #pragma unroll
            for (int i = 0; i < 6; i++) {
                float mv = l0;
                #pragma unroll
                for (int off = 16; off; off >>= 1)
                    mv = fminf(mv, __shfl_xor_sync(0xffffffffu, mv, off));
                if (lane == i) keep = mv;
                unsigned msk = __ballot_sync(0xffffffffu, l0 == mv);
                if (lane == (__ffs(msk) - 1)) {
                    l0 = l1; l1 = l2; l2 = l3; l3 = l4; l4 = l5; l5 = 3.4e38f;
                }
            }
            if (lane < 6) g_t6[g][q][trow * 4 + r][lane] = keep;
        }
        __syncthreads();
        if (tid == 0) {
            __threadfence();
            int old = atomicAdd(&g_qc[g], 1);
            S->merge = (old == NQ - 1);
        }
        __syncthreads();
        if (S->merge) {
            __threadfence();
            if (tid < 16) {
                int kk = *kp; if (kk > 5) kk = 5;
                float best[6];
                #pragma unroll
                for (int i = 0; i < 6; i++) best[i] = 3.4e38f;
                for (int qq = 0; qq < NQ; qq++) {
                    #pragma unroll
                    for (int i = 0; i < 6; i++) {
                        float v = g_t6[g][qq][tid][i];
                        if (v < best[5]) {
                            best[5] = v;
                            #pragma unroll
                            for (int j2 = 5; j2 > 0; j2--)
                                if (best[j2] < best[j2 - 1]) {
                                    float tm = best[j2]; best[j2] = best[j2 - 1]; best[j2 - 1] = tm;
                                }
                        }
                    }
                }
                g_logrho[row0 + tid] = logf(fmaxf(best[kk], 1e-12f));
            }
            if (tid == 0) g_qc[g] = 0;   // reset for graph replay
        }
    } else {
        // ================= PREP (128 threads, 8 elems/thread) ==============
        PrepS* P = (PrepS*)sm;
        const int col = bx - NBLK_KNN;
        float s1 = 0.f, s2 = 0.f;
        #pragma unroll
        for (int t = 0; t < 8; t++) {
            float v = act[(tid + 128 * t) * N_DIM + col];
            P->u[tid + 128 * t] = v;
            s1 += v;
            s2 += v * v;
        }
        P->red[tid] = s1; __syncthreads();
        for (int st = 64; st > 0; st >>= 1) {
            if (tid < st) P->red[tid] += P->red[tid + st];
            __syncthreads();
        }
        float tot1 = P->red[0]; __syncthreads();
        P->red[tid] = s2; __syncthreads();
        for (int st = 64; st > 0; st >>= 1) {
            if (tid < st) P->red[tid] += P->red[tid + st];
            __syncthreads();
        }
        if (tid == 0) {
            const float Bf = (float)B_ROWS;
            float mean = tot1 / Bf;
            float var  = (P->red[0] - Bf * mean * mean) / (Bf - 1.0f);
            float stdv = sqrtf(fmaxf(var, 0.f));
            float h    = fmaxf(1.06f * stdv * 0.25f, 1e-4f);
            float ih   = 1.0f / h;
            g_invh[col] = ih;
            g_zih[col]  = ih * ZF;
            P->scale    = ih * ZF;
        }
        __syncthreads();
        const float sc = P->scale;
        #pragma unroll
        for (int t = 0; t < 8; t++)
            P->u[tid + 128 * t] *= sc;

        for (int kk2 = 2; kk2 <= B_ROWS; kk2 <<= 1) {
            for (int jj = kk2 >> 1; jj > 0; jj >>= 1) {
                __syncthreads();
                #pragma unroll
                for (int t = 0; t < 8; t++) {
                    int i = tid + 128 * t;
                    int ixj = i ^ jj;
                    if (ixj > i) {
                        bool up = ((i & kk2) == 0);
                        float a = P->u[i], b = P->u[ixj];
                        if ((a > b) == up) { P->u[i] = b; P->u[ixj] = a; }
                    }
                }
            }
        }
        __syncthreads();
        #pragma unroll
        for (int t = 0; t < 8; t++)
            g_cols[col * B_ROWS + tid + 128 * t] = P->u[tid + 128 * t];
    }
}

// ---------------------------------------------------------------------------
// Kernel 2: KDE (float4 body, shared bounds) + final assembly.
// grid=(64,32), block=128.
// ---------------------------------------------------------------------------
__global__ __launch_bounds__(128)
void k2(const int* __restrict__ kp, float* __restrict__ out) {
    __shared__ __align__(16) float u[B_ROWS];
    __shared__ float sums[32][5];
    __shared__ int   bnd[4];
    __shared__ double dred[128];
    __shared__ int   sdone;

    const int tid   = threadIdx.x;
    const int lane  = tid & 31;
    const int w     = tid >> 5;
    const int col   = blockIdx.x;
    const int chunk = blockIdx.y;

    const float4* gc = (const float4*)(g_cols + col * B_ROWS);
    ((float4*)u)[tid]       = gc[tid];
    ((float4*)u)[tid + 128] = gc[tid + 128];
    __syncthreads();

    const float zih = g_zih[col];
    const int   q0  = chunk * 32;
    const float x   = u[q0 + lane];
    const float c2s = 2.0f * zih;

    if (tid < 4) {
        const float xmin = u[q0], xmax = u[q0 + 31];
        float tgt = (tid == 0) ? xmin - TS4 : (tid == 1) ? xmax + TS4
                  : (tid == 2) ? TS4 - xmin : c2s - TS4 - xmax;
        int pos = 0;
        #pragma unroll
        for (int step = 1024; step; step >>= 1) {
            int np = pos + step;
            if (np <= B_ROWS && u[np - 1] < tgt) pos = np;
        }
        bnd[tid] = pos;
    }
    __syncthreads();
    const int a0 = bnd[0], b0 = bnd[1], bL = bnd[2], aR = bnd[3];

    // main window: contiguous quarter per warp, float4 body
    const int len = b0 - a0;
    int lo = a0 + ((len * w) >> 2);
    int hi = a0 + ((len * (w + 1)) >> 2);
    float A0 = 0.f, A1 = 0.f, A2 = 0.f, A3 = 0.f;
    int j = lo;
    for (; j < hi && (j & 3); j++) { float d = x - u[j]; A0 += ex2(d * -d); }
    for (; j + 3 < hi; j += 4) {
        float4 y = *(const float4*)(u + j);
        float d0 = x - y.x, d1 = x - y.y, d2 = x - y.z, d3 = x - y.w;
        A0 += ex2(d0 * -d0);
        A1 += ex2(d1 * -d1);
        A2 += ex2(d2 * -d2);
        A3 += ex2(d3 * -d3);
    }
    for (; j < hi; j++) { float d = x - u[j]; A0 += ex2(d * -d); }
    // reflections
    for (j = w; j < bL; j += 4) { float s = x + u[j]; A1 += ex2(s * -s); }
    const float xc = x - c2s;
    for (j = aR + w; j < B_ROWS; j += 4) { float s = xc + u[j]; A0 += ex2(s * -s); }
    sums[lane][w] = (A0 + A1) + (A2 + A3);
    __syncthreads();

    if (w == 0) {
        const float Bf = (float)B_ROWS;
        const float scale = g_invh[col] * (1.0f / (Bf * 2.5066282746310002f));
        float tot = (sums[lane][0] + sums[lane][1]) + (sums[lane][2] + sums[lane][3]);
        float l = logf(tot * scale + 1e-8f);
        #pragma unroll
        for (int off = 16; off; off >>= 1)
            l += __shfl_xor_sync(0xffffffffu, l, off);
        if (lane == 0)
            g_partials[col * QCH + chunk] = l;
    }
    __syncthreads();

    if (tid == 0) {
        __threadfence();
        unsigned p = atomicAdd(&g_done, 1);
        sdone = (p == NBLK_KDE - 1);
    }
    __syncthreads();
    if (!sdone) return;
    __threadfence();

    if (tid < N_DIM) {
        float t = 0.f;
        #pragma unroll
        for (int c = 0; c < QCH; c++)
            t += g_partials[tid * QCH + c];
        out[1 + tid] = -t / (float)B_ROWS;
    }
    double s = 0.0;
    for (int i = tid; i < B_ROWS; i += 128) s += (double)g_logrho[i];
    dred[tid] = s; __syncthreads();
    for (int st = 64; st > 0; st >>= 1) {
        if (tid < st) dred[tid] += dred[tid + st];
        __syncthreads();
    }
    if (tid == 0) {
        const int k = *kp;
        const double EULER    = 0.5772156649015328606;
        const double DG_B     = 6.9309834448765934;     // psi(1024)
        const double LGAMMA33 = 81.55795945611503558;   // lgamma(64/2+1)
        const double LOG_PI   = 1.1447298858494001741;
        const double INV_LN2  = 1.4426950408889634074;
        double dg_k = -EULER;
        for (int i = 1; i < k; i++) dg_k += 1.0 / (double)i;
        double log_c_d = 0.5 * (double)N_DIM * LOG_PI - LGAMMA33;
        double mean_lr = dred[0] / (double)B_ROWS;
        double h_nats = -dg_k + DG_B + log_c_d + (double)N_DIM * 0.5 * mean_lr;
        out[0] = (float)(h_nats * INV_LN2);
    }
}

// ---------------------------------------------------------------------------
extern "C" void kernel_launch(void* const* d_in, const int* in_sizes, int n_in,
                              void* d_out, int out_size) {
    const float* act = (const float*)d_in[0];
    const int*   kp  = (const int*)d_in[1];
    float* out = (float*)d_out;
    (void)in_sizes; (void)n_in; (void)out_size;

    k1<<<NBLK_KNN + N_DIM, 128>>>(act, kp);
    dim3 g(N_DIM, QCH);
    k2<<<g, 128>>>(kp, out);
}